// round 12
// baseline (speedup 1.0000x reference)
#include <cuda_runtime.h>
#include <cstdint>

// PANLoss: dual-path memory experiment.
//   TMA ring (3 slots, 2 ahead): sim planes (sim CTAs), pr+pk (dice CTAs)
//   LDG direct: label maps (sim CTAs), rg+kg (dice CTAs), issued pre-wait.
// Grid 18x16 = 288 CTAs = 2/SM single wave. Private smem bins (proven).
// Inputs: 0 pred_regions f32, 1 regions_gt f32, 2 pred_kernels f32,
//         3 kernels_gt f32, 4 pred_similarities (16,4,640,640) f32,
//         5 text labels i32 [0,8], 6 kernel labels i32 [0,8]
// Output: 5 f32 scalars.

#define HW4    102400
#define NB     16
#define SIMB   10            // sim CTAs per batch: 10240 f4 each, 40 stages
#define DICB   8             // dice CTAs per batch: 12800 f4 each, 50 stages
#define NTH    256
#define NSEG   9
#define NACC   45            // 0-8 T2, 9-17 ct, 18-26 K2, 27-35 ck, 36-44 Ssd
#define EPSF   1e-5f
#define NPXF   409600.0f
#define NBLK   ((SIMB + DICB) * NB)     // 288
#define STG    256           // float4 per stream per stage
#define NST_S  40
#define NST_D  50
#define NSLOT  3

// dynamic smem layout (bytes); ring slot = 16KB (4 streams x 4KB max)
#define BUFSTRIDE 16384
#define OFF_BUF   0                       // 3 x 16384 = 49152
#define OFF_TP    49152                   // float4 [9*256] = 36864
#define OFF_KP    86016                   // float2 [9*256] = 18432
#define OFF_MBAR  104448                  // 3 x u64
#define OFF_LAST  104472                  // u32
#define DYN_SMEM  104480

__device__ float        g_hist[NB * NACC];   // zero at entry (reset in tail)
__device__ float        g_dice[NB * 8];
__device__ unsigned int g_sem;

__device__ __forceinline__ float tanh_fast(float x) {
    float t;
    asm("tanh.approx.f32 %0, %1;" : "=f"(t) : "f"(x));
    return t;
}
__device__ __forceinline__ uint32_t smem_u32(const void* p) {
    uint32_t a;
    asm("{ .reg .u64 t; cvta.to.shared.u64 t, %1; cvt.u32.u64 %0, t; }"
        : "=r"(a) : "l"(p));
    return a;
}
__device__ __forceinline__ void mbar_init(uint32_t a, uint32_t cnt) {
    asm volatile("mbarrier.init.shared.b64 [%0], %1;" :: "r"(a), "r"(cnt) : "memory");
}
__device__ __forceinline__ void mbar_expect_tx(uint32_t a, uint32_t tx) {
    asm volatile("mbarrier.arrive.expect_tx.shared.b64 _, [%0], %1;"
                 :: "r"(a), "r"(tx) : "memory");
}
__device__ __forceinline__ void mbar_wait(uint32_t a, uint32_t parity) {
    uint32_t done;
    asm volatile(
        "{\n\t.reg .pred p;\n\t"
        "mbarrier.try_wait.parity.acquire.cta.shared::cta.b64 p, [%1], %2;\n\t"
        "selp.b32 %0, 1, 0, p;\n\t}"
        : "=r"(done) : "r"(a), "r"(parity) : "memory");
    if (!done) {
        asm volatile(
            "{\n\t.reg .pred P1;\n\t"
            "W_%=:\n\t"
            "mbarrier.try_wait.parity.acquire.cta.shared::cta.b64 P1, [%0], %1, 0x989680;\n\t"
            "@P1 bra.uni D_%=;\n\t"
            "bra.uni W_%=;\n\t"
            "D_%=:\n\t}"
            :: "r"(a), "r"(parity) : "memory");
    }
}
__device__ __forceinline__ void bulk_g2s(uint32_t dst, const void* src,
                                         uint32_t bytes, uint32_t mbar) {
    asm volatile(
        "cp.async.bulk.shared::cluster.global.mbarrier::complete_tx::bytes "
        "[%0], [%1], %2, [%3];"
        :: "r"(dst), "l"(src), "r"(bytes), "r"(mbar) : "memory");
}
__device__ __forceinline__ float4 ldcg4(const float4* p) {
    float4 v;
    asm volatile("ld.global.cg.v4.f32 {%0,%1,%2,%3}, [%4];"
                 : "=f"(v.x), "=f"(v.y), "=f"(v.z), "=f"(v.w) : "l"(p));
    return v;
}
__device__ __forceinline__ int4 ldcg4i(const int4* p) {
    int4 v;
    asm volatile("ld.global.cg.v4.s32 {%0,%1,%2,%3}, [%4];"
                 : "=r"(v.x), "=r"(v.y), "=r"(v.z), "=r"(v.w) : "l"(p));
    return v;
}

extern __shared__ char smem_raw[];

__global__ __launch_bounds__(NTH) void pan_fused(
    const char* __restrict__ pr, const char* __restrict__ rg,
    const char* __restrict__ pk, const char* __restrict__ kg,
    const char* __restrict__ sim,
    const char* __restrict__ tl, const char* __restrict__ kl,
    float* __restrict__ out)
{
    const int b   = blockIdx.y;
    const int tid = threadIdx.x;

    const uint32_t sbase = smem_u32(smem_raw);
    const uint32_t mbar0 = sbase + OFF_MBAR;
    unsigned int* s_last = (unsigned int*)(smem_raw + OFF_LAST);

    if (tid == 0) {
        #pragma unroll
        for (int i = 0; i < NSLOT; i++) mbar_init(mbar0 + i * 8, 1);
    }

    if (blockIdx.x < SIMB) {
        // ========== SIM PATH: 4 planes via TMA, labels via LDG ==========
        float4* tpb = (float4*)(smem_raw + OFF_TP);   // {T2, Ssd, ct, pad}
        float2* kpb = (float2*)(smem_raw + OFF_KP);   // {K2, ck}
        #pragma unroll
        for (int i = 0; i < NSEG; i++) {
            tpb[i * NTH + tid] = make_float4(0.f, 0.f, 0.f, 0.f);
            kpb[i * NTH + tid] = make_float2(0.f, 0.f);
        }
        __syncthreads();    // bins + mbar_init visible

        const size_t simb = (size_t)b * 4 * HW4 * 16;
        const int4* __restrict__ tlb = (const int4*)(tl + (size_t)b * HW4 * 16);
        const int4* __restrict__ klb = (const int4*)(kl + (size_t)b * HW4 * 16);
        const int bx = blockIdx.x;
        const int base_f4 = bx * (HW4 / SIMB);        // 10240 f4 per CTA

#define SIM_ISSUE(s) do {                                                      \
        int sl_ = (s) % NSLOT;                                                 \
        uint32_t mb_  = mbar0 + sl_ * 8;                                       \
        uint32_t dst_ = sbase + OFF_BUF + sl_ * BUFSTRIDE;                     \
        size_t go_ = ((size_t)base_f4 + (size_t)(s) * STG) * 16;               \
        mbar_expect_tx(mb_, 16384u);                                           \
        bulk_g2s(dst_,          sim + simb + go_,                   4096, mb_);\
        bulk_g2s(dst_ + 4096,   sim + simb + (size_t)HW4*16 + go_,  4096, mb_);\
        bulk_g2s(dst_ + 8192,   sim + simb + (size_t)HW4*32 + go_,  4096, mb_);\
        bulk_g2s(dst_ + 12288,  sim + simb + (size_t)HW4*48 + go_,  4096, mb_);\
    } while (0)

        if (tid == 0) { SIM_ISSUE(0); SIM_ISSUE(1); }

#define SIM_PROC(s0x, s1x, s2x, s3x, tx, kx) do {                              \
        float s2_ = fmaf((s0x),(s0x), fmaf((s1x),(s1x),                        \
                    fmaf((s2x),(s2x), (s3x)*(s3x))));                          \
        float4 tv_ = tpb[(tx) * NTH + tid];                                    \
        tv_.x += s2_;                                                          \
        tv_.y += ((tx) == (kx)) ? s2_ : 0.0f;                                  \
        tv_.z += 1.0f;                                                         \
        tpb[(tx) * NTH + tid] = tv_;                                           \
        float2 kv_ = kpb[(kx) * NTH + tid];                                    \
        kv_.x += s2_; kv_.y += 1.0f;                                           \
        kpb[(kx) * NTH + tid] = kv_;                                           \
    } while (0)

        #pragma unroll 1
        for (int s = 0; s < NST_S; s++) {
            if (tid == 0 && s + 2 < NST_S) SIM_ISSUE(s + 2);
            // LDG labels for this stage BEFORE the TMA wait (overlaps)
            int g = base_f4 + s * STG + tid;
            int4 T = ldcg4i(tlb + g);
            int4 K = ldcg4i(klb + g);

            int sl = s % NSLOT;
            mbar_wait(mbar0 + sl * 8, (s / NSLOT) & 1);

            const float4* bp = (const float4*)(smem_raw + OFF_BUF + sl * BUFSTRIDE);
            float4 S0 = bp[tid];
            float4 S1 = bp[256 + tid];
            float4 S2 = bp[512 + tid];
            float4 S3 = bp[768 + tid];

            SIM_PROC(S0.x, S1.x, S2.x, S3.x, T.x, K.x);
            SIM_PROC(S0.y, S1.y, S2.y, S3.y, T.y, K.y);
            SIM_PROC(S0.z, S1.z, S2.z, S3.z, T.z, K.z);
            SIM_PROC(S0.w, S1.w, S2.w, S3.w, T.w, K.w);
            __syncthreads();
        }
#undef SIM_PROC
#undef SIM_ISSUE

        // ---- block-reduce private bins, flush ----
        #pragma unroll
        for (int s = NTH / 2; s >= 32; s >>= 1) {
            if (tid < s) {
                #pragma unroll
                for (int i = 0; i < NSEG; i++) {
                    float4 a0 = tpb[i * NTH + tid], b0 = tpb[i * NTH + tid + s];
                    a0.x += b0.x; a0.y += b0.y; a0.z += b0.z;
                    tpb[i * NTH + tid] = a0;
                    float2 c0 = kpb[i * NTH + tid], d0 = kpb[i * NTH + tid + s];
                    c0.x += d0.x; c0.y += d0.y;
                    kpb[i * NTH + tid] = c0;
                }
            }
            __syncthreads();
        }
        if (tid < 32) {
            #pragma unroll
            for (int i = 0; i < NSEG; i++) {
                float4 v = tpb[i * NTH + tid];
                float2 w = kpb[i * NTH + tid];
                #pragma unroll
                for (int o = 16; o; o >>= 1) {
                    v.x += __shfl_down_sync(0xffffffffu, v.x, o);
                    v.y += __shfl_down_sync(0xffffffffu, v.y, o);
                    v.z += __shfl_down_sync(0xffffffffu, v.z, o);
                    w.x += __shfl_down_sync(0xffffffffu, w.x, o);
                    w.y += __shfl_down_sync(0xffffffffu, w.y, o);
                }
                if (tid == 0) {
                    atomicAdd(&g_hist[b * NACC + i],      v.x);   // T2
                    atomicAdd(&g_hist[b * NACC + 36 + i], v.y);   // Ssd
                    atomicAdd(&g_hist[b * NACC + 9 + i],  v.z);   // ct
                    atomicAdd(&g_hist[b * NACC + 18 + i], w.x);   // K2
                    atomicAdd(&g_hist[b * NACC + 27 + i], w.y);   // ck
                }
            }
        }
    } else {
        // ========== DICE PATH: pr+pk via TMA, rg+kg via LDG ==========
        __syncthreads();    // mbar_init visibility
        const int dbx = blockIdx.x - SIMB;
        const size_t bb = (size_t)b * HW4 * 16;
        const float4* __restrict__ rgb = (const float4*)(rg + bb);
        const float4* __restrict__ kgb = (const float4*)(kg + bb);
        const int base_f4 = dbx * (HW4 / DICB);       // 12800 f4 per CTA

#define DICE_ISSUE(s) do {                                                     \
        int sl_ = (s) % NSLOT;                                                 \
        uint32_t mb_  = mbar0 + sl_ * 8;                                       \
        uint32_t dst_ = sbase + OFF_BUF + sl_ * BUFSTRIDE;                     \
        size_t go_ = ((size_t)base_f4 + (size_t)(s) * STG) * 16;               \
        mbar_expect_tx(mb_, 8192u);                                            \
        bulk_g2s(dst_,         pr + bb + go_, 4096, mb_);                      \
        bulk_g2s(dst_ + 4096,  pk + bb + go_, 4096, mb_);                      \
    } while (0)

        float St_r = 0.f, St2_r = 0.f, Sgt_r = 0.f, Sg_r = 0.f;
        float St_k = 0.f, St2_k = 0.f, Sgt_k = 0.f, Sg_k = 0.f;

        if (tid == 0) { DICE_ISSUE(0); DICE_ISSUE(1); }

#define DICE_PROC(ax, gx, cx, dx) do {                                         \
        float t1_ = tanh_fast(0.5f * (ax));                                    \
        St_r  += t1_;                                                          \
        St2_r  = fmaf(t1_, t1_, St2_r);                                        \
        Sgt_r  = fmaf(t1_, (gx), Sgt_r);                                       \
        Sg_r  += (gx);                                                         \
        float t2_ = tanh_fast(0.5f * (cx));                                    \
        St_k  += t2_;                                                          \
        St2_k  = fmaf(t2_, t2_, St2_k);                                        \
        Sgt_k  = fmaf(t2_, (dx), Sgt_k);                                       \
        Sg_k  += (dx);                                                         \
    } while (0)

        #pragma unroll 1
        for (int s = 0; s < NST_D; s++) {
            if (tid == 0 && s + 2 < NST_D) DICE_ISSUE(s + 2);
            int g = base_f4 + s * STG + tid;
            float4 G = ldcg4(rgb + g);
            float4 D = ldcg4(kgb + g);

            int sl = s % NSLOT;
            mbar_wait(mbar0 + sl * 8, (s / NSLOT) & 1);

            const float4* bp = (const float4*)(smem_raw + OFF_BUF + sl * BUFSTRIDE);
            float4 A = bp[tid];
            float4 C = bp[256 + tid];

            DICE_PROC(A.x, G.x, C.x, D.x);
            DICE_PROC(A.y, G.y, C.y, D.y);
            DICE_PROC(A.z, G.z, C.z, D.z);
            DICE_PROC(A.w, G.w, C.w, D.w);
            __syncthreads();
        }
#undef DICE_PROC
#undef DICE_ISSUE

        #pragma unroll
        for (int o = 16; o; o >>= 1) {
            St_r  += __shfl_down_sync(0xffffffffu, St_r,  o);
            St2_r += __shfl_down_sync(0xffffffffu, St2_r, o);
            Sgt_r += __shfl_down_sync(0xffffffffu, Sgt_r, o);
            Sg_r  += __shfl_down_sync(0xffffffffu, Sg_r,  o);
            St_k  += __shfl_down_sync(0xffffffffu, St_k,  o);
            St2_k += __shfl_down_sync(0xffffffffu, St2_k, o);
            Sgt_k += __shfl_down_sync(0xffffffffu, Sgt_k, o);
            Sg_k  += __shfl_down_sync(0xffffffffu, Sg_k,  o);
        }
        if ((tid & 31) == 0) {
            atomicAdd(&g_dice[b*8+0], St_r);  atomicAdd(&g_dice[b*8+1], St2_r);
            atomicAdd(&g_dice[b*8+2], Sgt_r); atomicAdd(&g_dice[b*8+3], Sg_r);
            atomicAdd(&g_dice[b*8+4], St_k);  atomicAdd(&g_dice[b*8+5], St2_k);
            atomicAdd(&g_dice[b*8+6], Sgt_k); atomicAdd(&g_dice[b*8+7], Sg_k);
        }
    }

    __threadfence();
    __syncthreads();
    if (tid == 0)
        *s_last = (atomicAdd(&g_sem, 1u) == (unsigned)(NBLK - 1)) ? 1u : 0u;
    __syncthreads();
    if (!*s_last) return;

    // ---------------- finalize (last block only) ----------------
    __threadfence();

    float lr = 0.f, lk = 0.f, lagg = 0.f, ldis = 0.f;
    if (tid < NB) {
        float T2[NSEG], ct[NSEG], K2[NSEG], ck[NSEG], Ssd[NSEG], a[8];
        #pragma unroll
        for (int i = 0; i < NSEG; i++) {
            T2[i]  = g_hist[tid * NACC + i];
            ct[i]  = g_hist[tid * NACC + 9 + i];
            K2[i]  = g_hist[tid * NACC + 18 + i];
            ck[i]  = g_hist[tid * NACC + 27 + i];
            Ssd[i] = g_hist[tid * NACC + 36 + i];
        }

        float St  = g_dice[tid*8+0], St2 = g_dice[tid*8+1];
        float Sgt = g_dice[tid*8+2], Sg  = g_dice[tid*8+3];
        float I = 0.5f * (Sgt + Sg);
        float P = 0.25f * (NPXF + 2.f * St + St2);
        lr = 1.0f - (2.0f * I + EPSF) / ((P + EPSF) + (Sg + EPSF));

        St  = g_dice[tid*8+4]; St2 = g_dice[tid*8+5];
        Sgt = g_dice[tid*8+6]; Sg  = g_dice[tid*8+7];
        I = 0.5f * (Sgt + Sg);
        P = 0.25f * (NPXF + 2.f * St + St2);
        lk = 1.0f - (2.0f * I + EPSF) / ((P + EPSF) + (Sg + EPSF));

        #pragma unroll 1
        for (int i = 1; i < NSEG; i++) {
            float inv = 1.0f / (ck[i] + 1.0f);
            float n2  = T2[i] - (2.0f * inv - inv * inv) * Ssd[i]
                        + inv * inv * (K2[i] - Ssd[i]);
            float nrm = sqrtf(fmaxf(n2, 0.0f));
            float d   = nrm - 0.5f;                    // SIGMA_AGG (no clamp)
            lagg += logf(d * d + 1.0f) / (ct[i] + 1.0f);
            float c1 = ck[i] + 0.001f;
            a[i - 1] = K2[i] / (c1 * c1);
        }
        #pragma unroll 1
        for (int i = 0; i < 8; i++)
            #pragma unroll 1
            for (int j = i + 1; j < 8; j++) {
                float pr_ = 3.0f - sqrtf(a[i] + a[j]); // SIGMA_DIS
                ldis += logf(pr_ * pr_ + 1.0f);
            }
        ldis *= (1.0f / 56.0f);
    }

    if (tid < 32) {
        #pragma unroll
        for (int o = 16; o; o >>= 1) {
            lr   += __shfl_down_sync(0xffffffffu, lr,   o);
            lk   += __shfl_down_sync(0xffffffffu, lk,   o);
            lagg += __shfl_down_sync(0xffffffffu, lagg, o);
            ldis += __shfl_down_sync(0xffffffffu, ldis, o);
        }
        if (tid == 0) {
            out[0] = lr + 0.5f * lk + 0.25f * (lagg + ldis);  // ALPHA, BETA
            out[1] = lr;
            out[2] = lk;
            out[3] = lagg;
            out[4] = ldis;
        }
    }
    __syncthreads();

    // reset scratch for next graph replay
    for (int i = tid; i < NB * NACC; i += NTH) g_hist[i] = 0.f;
    for (int i = tid; i < NB * 8;    i += NTH) g_dice[i] = 0.f;
    __threadfence();
    __syncthreads();
    if (tid == 0) g_sem = 0u;
}

extern "C" void kernel_launch(void* const* d_in, const int* in_sizes, int n_in,
                              void* d_out, int out_size) {
    (void)in_sizes; (void)n_in; (void)out_size;
    cudaFuncSetAttribute(pan_fused,
                         cudaFuncAttributeMaxDynamicSharedMemorySize, DYN_SMEM);
    dim3 grid(SIMB + DICB, NB);
    pan_fused<<<grid, NTH, DYN_SMEM>>>(
        (const char*)d_in[0], (const char*)d_in[1],
        (const char*)d_in[2], (const char*)d_in[3],
        (const char*)d_in[4],
        (const char*)d_in[5], (const char*)d_in[6],
        (float*)d_out);
}

// round 13
// speedup vs baseline: 1.0699x; 1.0699x over previous
#include <cuda_runtime.h>

// PANLoss: block-specialized LDG kernel, minimal smem chains.
//  sim: 2 smem RMW chains/px ({T2,Ssd} float2 + {K2} float) + packed u64 counts
//  dice: register accumulators
// 27KB smem -> 4 CTAs/SM. Grid (40+25)x16 = 1040 blocks.
// Inputs: 0 pred_regions f32, 1 regions_gt f32, 2 pred_kernels f32,
//         3 kernels_gt f32, 4 pred_similarities (16,4,640,640) f32,
//         5 text labels i32 [0,8], 6 kernel labels i32 [0,8]
// Output: 5 f32 scalars.

#define HW4    102400
#define NB     16
#define BPBS   40            // sim blocks/batch: 10 iters, 40 px/thread
#define BPBD   25            // dice blocks/batch: 16 iters
#define NTH    256
#define NSEG   9
#define NACC   45            // 0-8 T2, 9-17 ct, 18-26 K2, 27-35 ck, 36-44 Ssd
#define EPSF   1e-5f
#define NPXF   409600.0f
#define NBLK   ((BPBS + BPBD) * NB)
#define NWARP  (NTH / 32)

__device__ float        g_hist[NB * NACC];   // zero at entry (reset in tail)
__device__ float        g_dice[NB * 8];
__device__ unsigned int g_sem;

__device__ __forceinline__ float tanh_fast(float x) {
    float t;
    asm("tanh.approx.f32 %0, %1;" : "=f"(t) : "f"(x));
    return t;
}
__device__ __forceinline__ float4 ldcg4(const float4* p) {
    float4 v;
    asm volatile("ld.global.cg.v4.f32 {%0,%1,%2,%3}, [%4];"
                 : "=f"(v.x), "=f"(v.y), "=f"(v.z), "=f"(v.w) : "l"(p));
    return v;
}
__device__ __forceinline__ int4 ldcg4i(const int4* p) {
    int4 v;
    asm volatile("ld.global.cg.v4.s32 {%0,%1,%2,%3}, [%4];"
                 : "=r"(v.x), "=r"(v.y), "=r"(v.z), "=r"(v.w) : "l"(p));
    return v;
}

__global__ __launch_bounds__(NTH) void pan_fused(
    const float4* __restrict__ pr, const float4* __restrict__ rg,
    const float4* __restrict__ pk, const float4* __restrict__ kg,
    const float4* __restrict__ sim,
    const int4* __restrict__ tl, const int4* __restrict__ kl,
    float* __restrict__ out)
{
    __shared__ float2 sht_s[NSEG * NTH];   // {T2, Ssd} per thread per t-bin
    __shared__ float  shk_s[NSEG * NTH];   // {K2} per thread per k-bin
    __shared__ float  s_cw[NWARP][16];     // per-warp reduced counts
    __shared__ unsigned int s_last;
    const int b   = blockIdx.y;
    const int tid = threadIdx.x;
    const int wid = tid >> 5;
    const int lid = tid & 31;

    if (blockIdx.x < BPBS) {
        // ================= SIM PATH =================
        #pragma unroll
        for (int i = 0; i < NSEG; i++) {
            sht_s[i * NTH + tid] = make_float2(0.f, 0.f);
            shk_s[i * NTH + tid] = 0.f;
        }
        __syncthreads();

        const float4* __restrict__ smb = sim + (size_t)b * 4 * HW4;
        const int4*   __restrict__ tlb = tl + (size_t)b * HW4;
        const int4*   __restrict__ klb = kl + (size_t)b * HW4;

        float2* sht = &sht_s[tid];
        float*  shk = &shk_s[tid];
        unsigned long long ctp = 0ull, ckp = 0ull;  // 9 x 7-bit fields, <=40/th

        int g = blockIdx.x * NTH + tid;
        const int STR = BPBS * NTH;               // 10240

#define SIM_PROC(s0x, s1x, s2x, s3x, tx, kx) do {                              \
        float s2_ = fmaf((s0x),(s0x), fmaf((s1x),(s1x),                        \
                    fmaf((s2x),(s2x), (s3x)*(s3x))));                          \
        float2 tv_ = sht[(tx) * NTH];                                          \
        tv_.x += s2_;                                                          \
        tv_.y += ((tx) == (kx)) ? s2_ : 0.0f;                                  \
        sht[(tx) * NTH] = tv_;                                                 \
        shk[(kx) * NTH] += s2_;                                                \
        ctp += 1ULL << ((tx) * 7);                                             \
        ckp += 1ULL << ((kx) * 7);                                             \
    } while (0)

        #pragma unroll 2
        for (int it = 0; it < 10; it++) {
            float4 S0 = ldcg4(smb + g);
            float4 S1 = ldcg4(smb + HW4 + g);
            float4 S2 = ldcg4(smb + 2 * HW4 + g);
            float4 S3 = ldcg4(smb + 3 * HW4 + g);
            int4   T  = ldcg4i(tlb + g);
            int4   K  = ldcg4i(klb + g);

            SIM_PROC(S0.x, S1.x, S2.x, S3.x, T.x, K.x);
            SIM_PROC(S0.y, S1.y, S2.y, S3.y, T.y, K.y);
            SIM_PROC(S0.z, S1.z, S2.z, S3.z, T.z, K.z);
            SIM_PROC(S0.w, S1.w, S2.w, S3.w, T.w, K.w);
            g += STR;
        }
#undef SIM_PROC

        // ---- counts: unpack per-thread (each field <= 40, overflow-safe),
        //      warp-reduce, per-warp stash, block combine ----
        float cv[16];
        #pragma unroll
        for (int i = 0; i < 8; i++) {
            cv[i]     = (float)((unsigned int)(ctp >> (7 * (i + 1))) & 0x7Fu);
            cv[8 + i] = (float)((unsigned int)(ckp >> (7 * (i + 1))) & 0x7Fu);
        }
        #pragma unroll
        for (int o = 16; o; o >>= 1)
            #pragma unroll
            for (int i = 0; i < 16; i++)
                cv[i] += __shfl_down_sync(0xffffffffu, cv[i], o);
        if (lid == 0) {
            #pragma unroll
            for (int i = 0; i < 16; i++) s_cw[wid][i] = cv[i];
        }
        __syncthreads();
        if (tid < 16) {
            float v = 0.f;
            #pragma unroll
            for (int w = 0; w < NWARP; w++) v += s_cw[w][tid];
            int lbl = (tid & 7) + 1;
            int slot = (tid < 8) ? (9 + lbl) : (27 + lbl);   // ct / ck
            atomicAdd(&g_hist[b * NACC + slot], v);
        }

        // ---- block-reduce smem bins, flush ----
        #pragma unroll
        for (int s = NTH / 2; s >= 32; s >>= 1) {
            if (tid < s) {
                #pragma unroll
                for (int i = 0; i < NSEG; i++) {
                    float2 a0 = sht_s[i * NTH + tid], b0 = sht_s[i * NTH + tid + s];
                    a0.x += b0.x; a0.y += b0.y;
                    sht_s[i * NTH + tid] = a0;
                    shk_s[i * NTH + tid] += shk_s[i * NTH + tid + s];
                }
            }
            __syncthreads();
        }
        if (tid < 32) {
            #pragma unroll
            for (int i = 0; i < NSEG; i++) {
                float2 v = sht_s[i * NTH + tid];
                float  w = shk_s[i * NTH + tid];
                #pragma unroll
                for (int o = 16; o; o >>= 1) {
                    v.x += __shfl_down_sync(0xffffffffu, v.x, o);
                    v.y += __shfl_down_sync(0xffffffffu, v.y, o);
                    w   += __shfl_down_sync(0xffffffffu, w, o);
                }
                if (tid == 0) {
                    atomicAdd(&g_hist[b * NACC + i],      v.x);   // T2
                    atomicAdd(&g_hist[b * NACC + 36 + i], v.y);   // Ssd
                    atomicAdd(&g_hist[b * NACC + 18 + i], w);     // K2
                }
            }
        }
    } else {
        // ================= DICE PATH =================
        const int dbx = blockIdx.x - BPBS;
        const float4* __restrict__ prb = pr + (size_t)b * HW4;
        const float4* __restrict__ rgb = rg + (size_t)b * HW4;
        const float4* __restrict__ pkb = pk + (size_t)b * HW4;
        const float4* __restrict__ kgb = kg + (size_t)b * HW4;

        float St_r = 0.f, St2_r = 0.f, Sgt_r = 0.f, Sg_r = 0.f;
        float St_k = 0.f, St2_k = 0.f, Sgt_k = 0.f, Sg_k = 0.f;

        int g = dbx * NTH + tid;
        const int STR = BPBD * NTH;               // 6400

#define DICE_PROC(ax, gx, cx, dx) do {                                         \
        float t1_ = tanh_fast(0.5f * (ax));                                    \
        St_r  += t1_;                                                          \
        St2_r  = fmaf(t1_, t1_, St2_r);                                        \
        Sgt_r  = fmaf(t1_, (gx), Sgt_r);                                       \
        Sg_r  += (gx);                                                         \
        float t2_ = tanh_fast(0.5f * (cx));                                    \
        St_k  += t2_;                                                          \
        St2_k  = fmaf(t2_, t2_, St2_k);                                        \
        Sgt_k  = fmaf(t2_, (dx), Sgt_k);                                       \
        Sg_k  += (dx);                                                         \
    } while (0)

        #pragma unroll 2
        for (int it = 0; it < 16; it++) {
            float4 A = ldcg4(prb + g);
            float4 G = ldcg4(rgb + g);
            float4 C = ldcg4(pkb + g);
            float4 D = ldcg4(kgb + g);

            DICE_PROC(A.x, G.x, C.x, D.x);
            DICE_PROC(A.y, G.y, C.y, D.y);
            DICE_PROC(A.z, G.z, C.z, D.z);
            DICE_PROC(A.w, G.w, C.w, D.w);
            g += STR;
        }
#undef DICE_PROC

        #pragma unroll
        for (int o = 16; o; o >>= 1) {
            St_r  += __shfl_down_sync(0xffffffffu, St_r,  o);
            St2_r += __shfl_down_sync(0xffffffffu, St2_r, o);
            Sgt_r += __shfl_down_sync(0xffffffffu, Sgt_r, o);
            Sg_r  += __shfl_down_sync(0xffffffffu, Sg_r,  o);
            St_k  += __shfl_down_sync(0xffffffffu, St_k,  o);
            St2_k += __shfl_down_sync(0xffffffffu, St2_k, o);
            Sgt_k += __shfl_down_sync(0xffffffffu, Sgt_k, o);
            Sg_k  += __shfl_down_sync(0xffffffffu, Sg_k,  o);
        }
        if (lid == 0) {
            atomicAdd(&g_dice[b*8+0], St_r);  atomicAdd(&g_dice[b*8+1], St2_r);
            atomicAdd(&g_dice[b*8+2], Sgt_r); atomicAdd(&g_dice[b*8+3], Sg_r);
            atomicAdd(&g_dice[b*8+4], St_k);  atomicAdd(&g_dice[b*8+5], St2_k);
            atomicAdd(&g_dice[b*8+6], Sgt_k); atomicAdd(&g_dice[b*8+7], Sg_k);
        }
    }

    __threadfence();
    __syncthreads();
    if (tid == 0)
        s_last = (atomicAdd(&g_sem, 1u) == (unsigned)(NBLK - 1)) ? 1u : 0u;
    __syncthreads();
    if (!s_last) return;

    // ---------------- finalize (last block only) ----------------
    __threadfence();

    float lr = 0.f, lk = 0.f, lagg = 0.f, ldis = 0.f;
    if (tid < NB) {
        float T2[NSEG], ct[NSEG], K2[NSEG], ck[NSEG], Ssd[NSEG], a[8];
        #pragma unroll
        for (int i = 0; i < NSEG; i++) {
            T2[i]  = g_hist[tid * NACC + i];
            ct[i]  = g_hist[tid * NACC + 9 + i];
            K2[i]  = g_hist[tid * NACC + 18 + i];
            ck[i]  = g_hist[tid * NACC + 27 + i];
            Ssd[i] = g_hist[tid * NACC + 36 + i];
        }

        float St  = g_dice[tid*8+0], St2 = g_dice[tid*8+1];
        float Sgt = g_dice[tid*8+2], Sg  = g_dice[tid*8+3];
        float I = 0.5f * (Sgt + Sg);
        float P = 0.25f * (NPXF + 2.f * St + St2);
        lr = 1.0f - (2.0f * I + EPSF) / ((P + EPSF) + (Sg + EPSF));

        St  = g_dice[tid*8+4]; St2 = g_dice[tid*8+5];
        Sgt = g_dice[tid*8+6]; Sg  = g_dice[tid*8+7];
        I = 0.5f * (Sgt + Sg);
        P = 0.25f * (NPXF + 2.f * St + St2);
        lk = 1.0f - (2.0f * I + EPSF) / ((P + EPSF) + (Sg + EPSF));

        #pragma unroll 1
        for (int i = 1; i < NSEG; i++) {
            float inv = 1.0f / (ck[i] + 1.0f);
            float n2  = T2[i] - (2.0f * inv - inv * inv) * Ssd[i]
                        + inv * inv * (K2[i] - Ssd[i]);
            float nrm = sqrtf(fmaxf(n2, 0.0f));
            float d   = nrm - 0.5f;                    // SIGMA_AGG (no clamp)
            lagg += logf(d * d + 1.0f) / (ct[i] + 1.0f);
            float c1 = ck[i] + 0.001f;
            a[i - 1] = K2[i] / (c1 * c1);
        }
        #pragma unroll 1
        for (int i = 0; i < 8; i++)
            #pragma unroll 1
            for (int j = i + 1; j < 8; j++) {
                float pr_ = 3.0f - sqrtf(a[i] + a[j]); // SIGMA_DIS
                ldis += logf(pr_ * pr_ + 1.0f);
            }
        ldis *= (1.0f / 56.0f);
    }

    if (tid < 32) {
        #pragma unroll
        for (int o = 16; o; o >>= 1) {
            lr   += __shfl_down_sync(0xffffffffu, lr,   o);
            lk   += __shfl_down_sync(0xffffffffu, lk,   o);
            lagg += __shfl_down_sync(0xffffffffu, lagg, o);
            ldis += __shfl_down_sync(0xffffffffu, ldis, o);
        }
        if (tid == 0) {
            out[0] = lr + 0.5f * lk + 0.25f * (lagg + ldis);  // ALPHA, BETA
            out[1] = lr;
            out[2] = lk;
            out[3] = lagg;
            out[4] = ldis;
        }
    }
    __syncthreads();

    // reset scratch for next graph replay
    for (int i = tid; i < NB * NACC; i += NTH) g_hist[i] = 0.f;
    for (int i = tid; i < NB * 8;    i += NTH) g_dice[i] = 0.f;
    __threadfence();
    __syncthreads();
    if (tid == 0) g_sem = 0u;
}

extern "C" void kernel_launch(void* const* d_in, const int* in_sizes, int n_in,
                              void* d_out, int out_size) {
    (void)in_sizes; (void)n_in; (void)out_size;
    dim3 grid(BPBS + BPBD, NB);
    pan_fused<<<grid, NTH>>>(
        (const float4*)d_in[0], (const float4*)d_in[1],
        (const float4*)d_in[2], (const float4*)d_in[3],
        (const float4*)d_in[4],
        (const int4*)d_in[5],  (const int4*)d_in[6],
        (float*)d_out);
}